// round 9
// baseline (speedup 1.0000x reference)
#include <cuda_runtime.h>
#include <cstdint>
#include <cstddef>

// ---------------- problem constants ----------------
#define T_TOKENS   8192
#define DM         2048
#define DH         8192
#define NEXP       8
#define CAP        2560
#define NITEMS     (T_TOKENS*2)

// ---------------- device scratch (static) ----------
__device__ float g_buf [(size_t)NEXP*CAP*DM];     // dispatched x (tf32-rounded)
__device__ float g_h   [(size_t)NEXP*CAP*DH];     // hidden (tf32-rounded)
__device__ float g_oute[(size_t)NEXP*CAP*DM];     // expert outputs (fp32)
__device__ float g_w1r [(size_t)NEXP*(size_t)DM*DH]; // w1 tf32-rounded (same layout)
__device__ float g_w2r [(size_t)NEXP*(size_t)DM*DH]; // w2 tf32-rounded (same layout)
__device__ int   g_item_e  [NITEMS];
__device__ float g_item_w  [NITEMS];
__device__ int   g_item_pos[NITEMS];
__device__ int   g_count   [NEXP];

// ---------------- helpers --------------------------
__device__ __forceinline__ float tf32rn(float x) {
    uint32_t u; asm("cvt.rna.tf32.f32 %0, %1;" : "=r"(u) : "f"(x));
    return __uint_as_float(u);
}
__device__ __forceinline__ uint32_t smem_u32(const void* p) {
    uint32_t a;
    asm("{ .reg .u64 t; cvta.to.shared.u64 t, %1; cvt.u32.u64 %0, t; }" : "=r"(a) : "l"(p));
    return a;
}
__device__ __forceinline__ void cpasync16(uint32_t dst, const void* src) {
    asm volatile("cp.async.cg.shared.global [%0], [%1], 16;" :: "r"(dst), "l"(src));
}
__device__ __forceinline__ void cp_commit() {
    asm volatile("cp.async.commit_group;" ::: "memory");
}
__device__ __forceinline__ void cp_wait1() {
    asm volatile("cp.async.wait_group 1;" ::: "memory");
}
__device__ __forceinline__ void cp_wait0() {
    asm volatile("cp.async.wait_group 0;" ::: "memory");
}
__device__ __forceinline__ void mma_tf32(float* c, const uint32_t* a, const uint32_t* b) {
    asm volatile(
        "mma.sync.aligned.m16n8k8.row.col.f32.tf32.tf32.f32 "
        "{%0,%1,%2,%3}, {%4,%5,%6,%7}, {%8,%9}, {%0,%1,%2,%3};"
        : "+f"(c[0]), "+f"(c[1]), "+f"(c[2]), "+f"(c[3])
        : "r"(a[0]), "r"(a[1]), "r"(a[2]), "r"(a[3]), "r"(b[0]), "r"(b[1]));
}

// ---------------- 1) gating -------------------------
__global__ void gating_kernel(const float* __restrict__ x,
                              const float* __restrict__ gw) {
    int t = blockIdx.x;
    const float* xt = x + (size_t)t * DM;
    float acc[NEXP];
#pragma unroll
    for (int e = 0; e < NEXP; e++) acc[e] = 0.f;
    for (int d = threadIdx.x; d < DM; d += blockDim.x) {
        float xv = xt[d];
        const float* g = gw + (size_t)d * NEXP;
#pragma unroll
        for (int e = 0; e < NEXP; e++) acc[e] += xv * g[e];
    }
    __shared__ float red[NEXP][128];
#pragma unroll
    for (int e = 0; e < NEXP; e++) red[e][threadIdx.x] = acc[e];
    __syncthreads();
    for (int s = 64; s > 0; s >>= 1) {
        if (threadIdx.x < s) {
#pragma unroll
            for (int e = 0; e < NEXP; e++)
                red[e][threadIdx.x] += red[e][threadIdx.x + s];
        }
        __syncthreads();
    }
    if (threadIdx.x == 0) {
        float l[NEXP];
#pragma unroll
        for (int e = 0; e < NEXP; e++) l[e] = red[e][0];
        float m = l[0];
#pragma unroll
        for (int e = 1; e < NEXP; e++) m = fmaxf(m, l[e]);
        float p[NEXP]; float Z = 0.f;
#pragma unroll
        for (int e = 0; e < NEXP; e++) { p[e] = __expf(l[e] - m); Z += p[e]; }
        int i0 = 0;
#pragma unroll
        for (int e = 1; e < NEXP; e++) if (p[e] > p[i0]) i0 = e;
        int i1 = (i0 == 0) ? 1 : 0;
#pragma unroll
        for (int e = 0; e < NEXP; e++) if (e != i0 && p[e] > p[i1]) i1 = e;
        float w0 = p[i0] / Z, w1 = p[i1] / Z;
        float s = w0 + w1 + 1e-8f;
        g_item_e[2*t]   = i0;  g_item_e[2*t+1] = i1;
        g_item_w[2*t]   = w0 / s;
        g_item_w[2*t+1] = w1 / s;
    }
}

// ---------------- 2) serial positions ---------------
__global__ void position_kernel() {
    __shared__ int cnt[256][NEXP];
    int tid = threadIdx.x;
    int base = tid * (NITEMS / 256);
    int local[NEXP];
#pragma unroll
    for (int e = 0; e < NEXP; e++) local[e] = 0;
    for (int i = 0; i < NITEMS/256; i++) local[g_item_e[base + i]]++;
#pragma unroll
    for (int e = 0; e < NEXP; e++) cnt[tid][e] = local[e];
    __syncthreads();
    if (tid < NEXP) {
        int run = 0;
        for (int j = 0; j < 256; j++) { int c = cnt[j][tid]; cnt[j][tid] = run; run += c; }
        g_count[tid] = run < CAP ? run : CAP;
    }
    __syncthreads();
    int run[NEXP];
#pragma unroll
    for (int e = 0; e < NEXP; e++) run[e] = cnt[tid][e];
    for (int i = 0; i < NITEMS/256; i++) {
        int e = g_item_e[base + i];
        g_item_pos[base + i] = run[e]++;
    }
}

// ---------------- 3) dispatch (tf32 round) ----------
__global__ void dispatch_kernel(const float* __restrict__ x) {
    int i = blockIdx.x;
    int pos = g_item_pos[i];
    if (pos >= CAP) return;
    int e = g_item_e[i];
    int t = i >> 1;
    const float4* src = (const float4*)(x + (size_t)t * DM);
    float4* dst = (float4*)(g_buf + ((size_t)e * CAP + pos) * DM);
    for (int j = threadIdx.x; j < DM/4; j += blockDim.x) {
        float4 v = src[j];
        v.x = tf32rn(v.x); v.y = tf32rn(v.y); v.z = tf32rn(v.z); v.w = tf32rn(v.w);
        dst[j] = v;
    }
}

// ---------------- 3b) weight tf32 pre-round ---------
__global__ void weight_cvt_kernel(const float* __restrict__ in,
                                  float* __restrict__ out, size_t n4) {
    size_t i = (size_t)blockIdx.x * blockDim.x + threadIdx.x;
    size_t stride = (size_t)gridDim.x * blockDim.x;
    const float4* I = (const float4*)in;
    float4* O = (float4*)out;
    for (; i < n4; i += stride) {
        float4 v = I[i];
        v.x = tf32rn(v.x); v.y = tf32rn(v.y); v.z = tf32rn(v.z); v.w = tf32rn(v.w);
        O[i] = v;
    }
}

// ---------------- 4) HMMA TF32 GEMM -----------------
// C[e] = act(A[e] @ B[e] + bias[e]);  A:[CAP][K], B:[K][N] (both tf32-valued fp32)
// CTA 128x128x32, 256 threads, 8 warps of 64x32, 3-stage cp.async pipeline.
// n-relabeled B fragments: MMA ni covers global cols wn + j*4 + ni, so each
// thread's 4 b-values per k-row are contiguous -> LDS.128 (2 per kk).
#define GSMEM (3*(128*32 + 32*128)*4)   // 96 KB

template<bool RELU, bool CVT>
__global__ void __launch_bounds__(256, 2)
moe_gemm(const float* __restrict__ Aall, const float* __restrict__ Ball,
         const float* __restrict__ biasall, float* __restrict__ Call,
         int N, int K) {
    int e  = blockIdx.z;
    int bm = blockIdx.y * 128;
    int bn = blockIdx.x * 128;
    if (bm >= g_count[e]) return;

    const float* A = Aall + (size_t)e * CAP * K + (size_t)bm * K;
    const float* B = Ball + (size_t)e * K * N + bn;
    const float* bias = biasall + (size_t)e * N + bn;
    float* C = Call + (size_t)e * CAP * N;

    extern __shared__ float smem[];
    uint32_t sbase = smem_u32(smem);

    int tid = threadIdx.x;
    int wid = tid >> 5, lane = tid & 31;
    int gr = lane >> 2, tg = lane & 3;
    int wm = (wid & 1) * 64, wn = (wid >> 1) * 32;   // 2x4 warp grid, 64x32 tiles

    // staging assignments (256 threads)
    int a_r = tid >> 1;             // A row 0..127
    int a_h = tid & 1;              // chunk half (4 chunks each)
    int b_r = tid >> 3;             // B row 0..31
    int b_c = tid & 7;              // B chunk phase (4 chunks each)
    const float* aRow = A + (size_t)a_r * K;
    const float* bRow = B + (size_t)b_r * N;

    float acc[4][4][4];
#pragma unroll
    for (int mi = 0; mi < 4; mi++)
#pragma unroll
        for (int ni = 0; ni < 4; ni++)
#pragma unroll
            for (int r = 0; r < 4; r++) acc[mi][ni][r] = 0.f;

    int NB = K / 32;

    // stage loader: buffer buf (0..2), k offset kbig*32
    auto stage = [&](int buf, int kbig) {
        uint32_t aDst = sbase + buf * 16384 + a_r * 128;          // bytes
        const float* aSrc = aRow + kbig * 32;
#pragma unroll
        for (int j = 0; j < 4; j++) {
            int c = a_h * 4 + j;
            cpasync16(aDst + (((uint32_t)(c ^ (a_r & 7))) << 4), aSrc + c * 4);
        }
        uint32_t bDst = sbase + 49152 + buf * 16384 + b_r * 512;
        const float* bSrc = bRow + (size_t)kbig * 32 * N;
#pragma unroll
        for (int j = 0; j < 4; j++) {
            int c = b_c + j * 8;
            cpasync16(bDst + (((uint32_t)(c ^ ((b_r & 3) << 1))) << 4), bSrc + c * 4);
        }
    };

    // prologue: stages 0 and 1 in flight
    stage(0, 0); cp_commit();
    stage(1, 1); cp_commit();

    // B fragment read: chunk (wn/4 + gr) ^ ((k&3)<<1), k&3 == tg for both rows
    int bChunkSw = ((wn >> 2) + gr) ^ (tg << 1);    // 16B chunk index in 512B row

    int buf = 0;
    for (int big = 0; big < NB; big++) {
        if (big + 2 < NB) cp_wait1(); else cp_wait0();
        __syncthreads();   // single barrier per iteration

        if (big + 2 < NB) {
            int nbuf = buf + 2; if (nbuf >= 3) nbuf -= 3;
            stage(nbuf, big + 2);
            cp_commit();
        }

        const float* sA = smem + buf * 4096;
        const float* sB = smem + 12288 + buf * 4096;
#pragma unroll
        for (int kk = 0; kk < 32; kk += 8) {
            uint32_t a[4][4];
#pragma unroll
            for (int mi = 0; mi < 4; mi++) {
                int m0 = wm + mi * 16 + gr;
                int k0 = (kk + tg) ^ (gr << 2);
                int k1 = (kk + tg + 4) ^ (gr << 2);
                a[mi][0] = __float_as_uint(sA[m0 * 32 + k0]);
                a[mi][1] = __float_as_uint(sA[(m0 + 8) * 32 + k0]);
                a[mi][2] = __float_as_uint(sA[m0 * 32 + k1]);
                a[mi][3] = __float_as_uint(sA[(m0 + 8) * 32 + k1]);
            }
            // B: two LDS.128 cover all 4 ni fragments
            float4 f0 = *(const float4*)(sB + (kk + tg) * 128 + bChunkSw * 4);
            float4 f1 = *(const float4*)(sB + (kk + tg + 4) * 128 + bChunkSw * 4);
            uint32_t b[4][2];
            b[0][0] = __float_as_uint(f0.x); b[0][1] = __float_as_uint(f1.x);
            b[1][0] = __float_as_uint(f0.y); b[1][1] = __float_as_uint(f1.y);
            b[2][0] = __float_as_uint(f0.z); b[2][1] = __float_as_uint(f1.z);
            b[3][0] = __float_as_uint(f0.w); b[3][1] = __float_as_uint(f1.w);
#pragma unroll
            for (int mi = 0; mi < 4; mi++)
#pragma unroll
                for (int ni = 0; ni < 4; ni++)
                    mma_tf32(acc[mi][ni], a[mi], b[ni]);
        }

        buf++; if (buf >= 3) buf = 0;
    }

    // epilogue: thread covers contiguous cols wn+8tg .. wn+8tg+7
    int colb = wn + 8 * tg;
    float4 bb0 = *(const float4*)(bias + colb);
    float4 bb1 = *(const float4*)(bias + colb + 4);
#pragma unroll
    for (int mi = 0; mi < 4; mi++) {
        int row0 = bm + wm + mi * 16 + gr;
        int row1 = row0 + 8;
        float4 v00, v01, v10, v11;
        v00.x = acc[mi][0][0] + bb0.x; v00.y = acc[mi][1][0] + bb0.y;
        v00.z = acc[mi][2][0] + bb0.z; v00.w = acc[mi][3][0] + bb0.w;
        v01.x = acc[mi][0][1] + bb1.x; v01.y = acc[mi][1][1] + bb1.y;
        v01.z = acc[mi][2][1] + bb1.z; v01.w = acc[mi][3][1] + bb1.w;
        v10.x = acc[mi][0][2] + bb0.x; v10.y = acc[mi][1][2] + bb0.y;
        v10.z = acc[mi][2][2] + bb0.z; v10.w = acc[mi][3][2] + bb0.w;
        v11.x = acc[mi][0][3] + bb1.x; v11.y = acc[mi][1][3] + bb1.y;
        v11.z = acc[mi][2][3] + bb1.z; v11.w = acc[mi][3][3] + bb1.w;
        if (RELU) {
            v00.x = fmaxf(v00.x, 0.f); v00.y = fmaxf(v00.y, 0.f);
            v00.z = fmaxf(v00.z, 0.f); v00.w = fmaxf(v00.w, 0.f);
            v01.x = fmaxf(v01.x, 0.f); v01.y = fmaxf(v01.y, 0.f);
            v01.z = fmaxf(v01.z, 0.f); v01.w = fmaxf(v01.w, 0.f);
            v10.x = fmaxf(v10.x, 0.f); v10.y = fmaxf(v10.y, 0.f);
            v10.z = fmaxf(v10.z, 0.f); v10.w = fmaxf(v10.w, 0.f);
            v11.x = fmaxf(v11.x, 0.f); v11.y = fmaxf(v11.y, 0.f);
            v11.z = fmaxf(v11.z, 0.f); v11.w = fmaxf(v11.w, 0.f);
        }
        if (CVT) {
            v00.x = tf32rn(v00.x); v00.y = tf32rn(v00.y);
            v00.z = tf32rn(v00.z); v00.w = tf32rn(v00.w);
            v01.x = tf32rn(v01.x); v01.y = tf32rn(v01.y);
            v01.z = tf32rn(v01.z); v01.w = tf32rn(v01.w);
            v10.x = tf32rn(v10.x); v10.y = tf32rn(v10.y);
            v10.z = tf32rn(v10.z); v10.w = tf32rn(v10.w);
            v11.x = tf32rn(v11.x); v11.y = tf32rn(v11.y);
            v11.z = tf32rn(v11.z); v11.w = tf32rn(v11.w);
        }
        *(float4*)(C + (size_t)row0 * N + bn + colb)     = v00;
        *(float4*)(C + (size_t)row0 * N + bn + colb + 4) = v01;
        *(float4*)(C + (size_t)row1 * N + bn + colb)     = v10;
        *(float4*)(C + (size_t)row1 * N + bn + colb + 4) = v11;
    }
}

// ---------------- 5) combine ------------------------
__global__ void combine_kernel(float* __restrict__ out) {
    int t = blockIdx.x;
    int i0 = 2 * t, i1 = 2 * t + 1;
    int e0 = g_item_e[i0], e1 = g_item_e[i1];
    int p0 = g_item_pos[i0], p1 = g_item_pos[i1];
    float w0 = (p0 < CAP) ? g_item_w[i0] : 0.f;
    float w1 = (p1 < CAP) ? g_item_w[i1] : 0.f;
    if (p0 >= CAP) p0 = CAP - 1;
    if (p1 >= CAP) p1 = CAP - 1;
    const float4* s0 = (const float4*)(g_oute + ((size_t)e0 * CAP + p0) * DM);
    const float4* s1 = (const float4*)(g_oute + ((size_t)e1 * CAP + p1) * DM);
    float4* dst = (float4*)(out + (size_t)t * DM);
    for (int j = threadIdx.x; j < DM/4; j += blockDim.x) {
        float4 a = s0[j], b = s1[j];
        float4 r;
        r.x = w0 * a.x + w1 * b.x;
        r.y = w0 * a.y + w1 * b.y;
        r.z = w0 * a.z + w1 * b.z;
        r.w = w0 * a.w + w1 * b.w;
        dst[j] = r;
    }
}

// ---------------- launcher --------------------------
extern "C" void kernel_launch(void* const* d_in, const int* in_sizes, int n_in,
                              void* d_out, int out_size) {
    const float* x  = (const float*)d_in[0];
    const float* gw = (const float*)d_in[1];
    const float* w1 = (const float*)d_in[2];
    const float* b1 = (const float*)d_in[3];
    const float* w2 = (const float*)d_in[4];
    const float* b2 = (const float*)d_in[5];
    float* out = (float*)d_out;

    void *pbuf, *ph, *poute, *pw1r, *pw2r;
    cudaGetSymbolAddress(&pbuf,  g_buf);
    cudaGetSymbolAddress(&ph,    g_h);
    cudaGetSymbolAddress(&poute, g_oute);
    cudaGetSymbolAddress(&pw1r,  g_w1r);
    cudaGetSymbolAddress(&pw2r,  g_w2r);

    cudaFuncSetAttribute(moe_gemm<true,  true >, cudaFuncAttributeMaxDynamicSharedMemorySize, GSMEM);
    cudaFuncSetAttribute(moe_gemm<false, false>, cudaFuncAttributeMaxDynamicSharedMemorySize, GSMEM);

    gating_kernel<<<T_TOKENS, 128>>>(x, gw);
    position_kernel<<<1, 256>>>();
    dispatch_kernel<<<NITEMS, 128>>>(x);

    // pre-round weights to tf32 (same layout, removes all in-loop cvt)
    size_t wn4 = (size_t)NEXP * DM * DH / 4;
    weight_cvt_kernel<<<2048, 256>>>(w1, (float*)pw1r, wn4);
    weight_cvt_kernel<<<2048, 256>>>(w2, (float*)pw2r, wn4);

    // h = relu(buf @ w1 + b1): N=DH, K=DM
    moe_gemm<true,  true ><<<dim3(DH/128, CAP/128, NEXP), 256, GSMEM>>>(
        (const float*)pbuf, (const float*)pw1r, b1, (float*)ph, DH, DM);
    // oute = h @ w2 + b2: N=DM, K=DH
    moe_gemm<false, false><<<dim3(DM/128, CAP/128, NEXP), 256, GSMEM>>>(
        (const float*)ph, (const float*)pw2r, b2, (float*)poute, DM, DH);

    combine_kernel<<<T_TOKENS, 128>>>(out);
}

// round 10
// speedup vs baseline: 1.8814x; 1.8814x over previous
#include <cuda_runtime.h>
#include <cuda_fp16.h>
#include <cstdint>
#include <cstddef>

// ---------------- problem constants ----------------
#define T_TOKENS   8192
#define DM         2048
#define DH         8192
#define NEXP       8
#define CAP        2560
#define NITEMS     (T_TOKENS*2)

// ---------------- device scratch (static) ----------
__device__ __half g_buf [(size_t)NEXP*CAP*DM];      // dispatched x (fp16)
__device__ __half g_h   [(size_t)NEXP*CAP*DH];      // hidden (fp16)
__device__ float  g_oute[(size_t)NEXP*CAP*DM];      // expert outputs (fp32)
__device__ __half g_w1t [(size_t)NEXP*(size_t)DM*DH]; // w1^T: [E][DH][DM] fp16
__device__ __half g_w2t [(size_t)NEXP*(size_t)DM*DH]; // w2^T: [E][DM][DH] fp16
__device__ int    g_item_e  [NITEMS];
__device__ float  g_item_w  [NITEMS];
__device__ int    g_item_pos[NITEMS];
__device__ int    g_count   [NEXP];

// ---------------- helpers --------------------------
__device__ __forceinline__ uint32_t smem_u32(const void* p) {
    uint32_t a;
    asm("{ .reg .u64 t; cvta.to.shared.u64 t, %1; cvt.u32.u64 %0, t; }" : "=r"(a) : "l"(p));
    return a;
}
__device__ __forceinline__ void cpasync16(uint32_t dst, const void* src) {
    asm volatile("cp.async.cg.shared.global [%0], [%1], 16;" :: "r"(dst), "l"(src));
}
__device__ __forceinline__ void cp_commit() {
    asm volatile("cp.async.commit_group;" ::: "memory");
}
__device__ __forceinline__ void cp_wait1() {
    asm volatile("cp.async.wait_group 1;" ::: "memory");
}
__device__ __forceinline__ void cp_wait0() {
    asm volatile("cp.async.wait_group 0;" ::: "memory");
}
__device__ __forceinline__ void mma_f16(float* c, const uint32_t* a, const uint32_t* b) {
    asm volatile(
        "mma.sync.aligned.m16n8k16.row.col.f32.f16.f16.f32 "
        "{%0,%1,%2,%3}, {%4,%5,%6,%7}, {%8,%9}, {%0,%1,%2,%3};"
        : "+f"(c[0]), "+f"(c[1]), "+f"(c[2]), "+f"(c[3])
        : "r"(a[0]), "r"(a[1]), "r"(a[2]), "r"(a[3]), "r"(b[0]), "r"(b[1]));
}

// ---------------- 1) gating -------------------------
__global__ void gating_kernel(const float* __restrict__ x,
                              const float* __restrict__ gw) {
    int t = blockIdx.x;
    const float* xt = x + (size_t)t * DM;
    float acc[NEXP];
#pragma unroll
    for (int e = 0; e < NEXP; e++) acc[e] = 0.f;
    for (int d = threadIdx.x; d < DM; d += blockDim.x) {
        float xv = xt[d];
        const float* g = gw + (size_t)d * NEXP;
#pragma unroll
        for (int e = 0; e < NEXP; e++) acc[e] += xv * g[e];
    }
    __shared__ float red[NEXP][128];
#pragma unroll
    for (int e = 0; e < NEXP; e++) red[e][threadIdx.x] = acc[e];
    __syncthreads();
    for (int s = 64; s > 0; s >>= 1) {
        if (threadIdx.x < s) {
#pragma unroll
            for (int e = 0; e < NEXP; e++)
                red[e][threadIdx.x] += red[e][threadIdx.x + s];
        }
        __syncthreads();
    }
    if (threadIdx.x == 0) {
        float l[NEXP];
#pragma unroll
        for (int e = 0; e < NEXP; e++) l[e] = red[e][0];
        float m = l[0];
#pragma unroll
        for (int e = 1; e < NEXP; e++) m = fmaxf(m, l[e]);
        float p[NEXP]; float Z = 0.f;
#pragma unroll
        for (int e = 0; e < NEXP; e++) { p[e] = __expf(l[e] - m); Z += p[e]; }
        int i0 = 0;
#pragma unroll
        for (int e = 1; e < NEXP; e++) if (p[e] > p[i0]) i0 = e;
        int i1 = (i0 == 0) ? 1 : 0;
#pragma unroll
        for (int e = 0; e < NEXP; e++) if (e != i0 && p[e] > p[i1]) i1 = e;
        float w0 = p[i0] / Z, w1 = p[i1] / Z;
        float s = w0 + w1 + 1e-8f;
        g_item_e[2*t]   = i0;  g_item_e[2*t+1] = i1;
        g_item_w[2*t]   = w0 / s;
        g_item_w[2*t+1] = w1 / s;
    }
}

// ---------------- 2) serial positions ---------------
__global__ void position_kernel() {
    __shared__ int cnt[256][NEXP];
    int tid = threadIdx.x;
    int base = tid * (NITEMS / 256);
    int local[NEXP];
#pragma unroll
    for (int e = 0; e < NEXP; e++) local[e] = 0;
    for (int i = 0; i < NITEMS/256; i++) local[g_item_e[base + i]]++;
#pragma unroll
    for (int e = 0; e < NEXP; e++) cnt[tid][e] = local[e];
    __syncthreads();
    if (tid < NEXP) {
        int run = 0;
        for (int j = 0; j < 256; j++) { int c = cnt[j][tid]; cnt[j][tid] = run; run += c; }
        g_count[tid] = run < CAP ? run : CAP;
    }
    __syncthreads();
    int run[NEXP];
#pragma unroll
    for (int e = 0; e < NEXP; e++) run[e] = cnt[tid][e];
    for (int i = 0; i < NITEMS/256; i++) {
        int e = g_item_e[base + i];
        g_item_pos[base + i] = run[e]++;
    }
}

// ---------------- 3) dispatch (fp16 convert) --------
__global__ void dispatch_kernel(const float* __restrict__ x) {
    int i = blockIdx.x;
    int pos = g_item_pos[i];
    if (pos >= CAP) return;
    int e = g_item_e[i];
    int t = i >> 1;
    const float4* src = (const float4*)(x + (size_t)t * DM);
    __half2* dst = (__half2*)(g_buf + ((size_t)e * CAP + pos) * DM);
    for (int j = threadIdx.x; j < DM/4; j += blockDim.x) {
        float4 v = src[j];
        dst[2*j]   = __floats2half2_rn(v.x, v.y);
        dst[2*j+1] = __floats2half2_rn(v.z, v.w);
    }
}

// ---------------- 3b) weight transpose + fp16 -------
// in: [E][R][C] f32 -> out: [E][C][R] half
__global__ void transpose_cvt_half(const float* __restrict__ in,
                                   __half* __restrict__ out, int R, int C) {
    __shared__ float t[32][33];
    int e = blockIdx.z;
    const float* I = in + (size_t)e * R * C;
    __half* O = out + (size_t)e * R * C;
    int c0 = blockIdx.x * 32, r0 = blockIdx.y * 32;
    int tx = threadIdx.x, ty = threadIdx.y;   // block (32,8)
#pragma unroll
    for (int i = 0; i < 4; i++)
        t[ty + 8*i][tx] = I[(size_t)(r0 + ty + 8*i) * C + c0 + tx];
    __syncthreads();
    int p = ty * 32 + tx;
#pragma unroll
    for (int q = 0; q < 2; q++) {
        int pp = p + q * 256;
        int cl = pp >> 4, rp = pp & 15;
        __half2 h = __floats2half2_rn(t[2*rp][cl], t[2*rp+1][cl]);
        *(__half2*)(O + (size_t)(c0 + cl) * R + r0 + 2*rp) = h;
    }
}

// ---------------- 4) HMMA FP16 GEMM -----------------
// C[e] = act(A[e] @ Bt[e]^T + bias[e])
// A:[CAP][K] half (k-major), Bt:[N][K] half (k-major).
// CTA 128x128, K-step 64, 256 thr, 8 warps of 64x32, 3-stage cp.async.
// smem rows 128B (64 halfs... K=64 halfs = 128B), swizzle chunk ^ (row&7).
#define STGSZ 32768
#define GSMEM (3*STGSZ)   // 96 KB

template<bool RELU, bool HALFOUT>
__global__ void __launch_bounds__(256, 2)
moe_gemm(const __half* __restrict__ Aall, const __half* __restrict__ Btall,
         const float* __restrict__ biasall, void* __restrict__ Call,
         int N, int K) {
    int e  = blockIdx.z;
    int bm = blockIdx.y * 128;
    int bn = blockIdx.x * 128;
    if (bm >= g_count[e]) return;

    const __half* A  = Aall  + (size_t)e * CAP * K + (size_t)bm * K;
    const __half* Bt = Btall + (size_t)e * N * K + (size_t)bn * K;
    const float* bias = biasall + (size_t)e * N + bn;

    extern __shared__ char smem[];
    uint32_t sbase = smem_u32(smem);

    int tid = threadIdx.x;
    int wid = tid >> 5, lane = tid & 31;
    int gr = lane >> 2, tg = lane & 3;
    int wm = (wid & 1) * 64, wn = (wid >> 1) * 32;   // 2x4 warp grid, 64x32 tiles

    // staging: row a_r (both A and Bt tiles), 2 threads per row, 4 chunks each
    int a_r = tid >> 1;             // 0..127
    int a_h = tid & 1;
    const __half* aRow = A  + (size_t)a_r * K;
    const __half* bRow = Bt + (size_t)a_r * K;

    float acc[4][4][4];
#pragma unroll
    for (int mi = 0; mi < 4; mi++)
#pragma unroll
        for (int ni = 0; ni < 4; ni++)
#pragma unroll
            for (int r = 0; r < 4; r++) acc[mi][ni][r] = 0.f;

    int NB = K / 64;

    auto stage = [&](int buf, int kbig) {
        uint32_t aDst = sbase + buf * STGSZ + a_r * 128;
        const __half* aSrc = aRow + kbig * 64;
#pragma unroll
        for (int j = 0; j < 4; j++) {
            int c = a_h * 4 + j;
            cpasync16(aDst + (((uint32_t)(c ^ (a_r & 7))) << 4), aSrc + c * 8);
        }
        uint32_t bDst = sbase + buf * STGSZ + 16384 + a_r * 128;
        const __half* bSrc = bRow + kbig * 64;
#pragma unroll
        for (int j = 0; j < 4; j++) {
            int c = a_h * 4 + j;
            cpasync16(bDst + (((uint32_t)(c ^ (a_r & 7))) << 4), bSrc + c * 8);
        }
    };

    stage(0, 0); cp_commit();
    stage(1, 1); cp_commit();

    int buf = 0;
    for (int big = 0; big < NB; big++) {
        if (big + 2 < NB) cp_wait1(); else cp_wait0();
        __syncthreads();   // single barrier per iteration

        if (big + 2 < NB) {
            int nbuf = buf + 2; if (nbuf >= 3) nbuf -= 3;
            stage(nbuf, big + 2);
            cp_commit();
        }

        const char* sA = smem + buf * STGSZ;
        const char* sB = sA + 16384;
#pragma unroll
        for (int k16 = 0; k16 < 64; k16 += 16) {
            int ch0 = k16 >> 3;   // 0,2,4,6
            uint32_t a[4][4];
#pragma unroll
            for (int mi = 0; mi < 4; mi++) {
                int m0 = wm + mi * 16 + gr;
                uint32_t sw  = (uint32_t)(((ch0 ^ (m0 & 7)) << 4) | (tg << 2));
                uint32_t sw2 = (uint32_t)((((ch0 + 1) ^ (m0 & 7)) << 4) | (tg << 2));
                a[mi][0] = *(const uint32_t*)(sA + m0 * 128 + sw);
                a[mi][1] = *(const uint32_t*)(sA + (m0 + 8) * 128 + sw);
                a[mi][2] = *(const uint32_t*)(sA + m0 * 128 + sw2);
                a[mi][3] = *(const uint32_t*)(sA + (m0 + 8) * 128 + sw2);
            }
            uint32_t b[4][2];
#pragma unroll
            for (int ni = 0; ni < 4; ni++) {
                int n0 = wn + ni * 8 + gr;
                uint32_t swb  = (uint32_t)(((ch0 ^ (n0 & 7)) << 4) | (tg << 2));
                uint32_t swb2 = (uint32_t)((((ch0 + 1) ^ (n0 & 7)) << 4) | (tg << 2));
                b[ni][0] = *(const uint32_t*)(sB + n0 * 128 + swb);
                b[ni][1] = *(const uint32_t*)(sB + n0 * 128 + swb2);
            }
#pragma unroll
            for (int mi = 0; mi < 4; mi++)
#pragma unroll
                for (int ni = 0; ni < 4; ni++)
                    mma_f16(acc[mi][ni], a[mi], b[ni]);
        }

        buf++; if (buf >= 3) buf = 0;
    }

    // epilogue
#pragma unroll
    for (int mi = 0; mi < 4; mi++) {
        int row0 = bm + wm + mi * 16 + gr;
        int row1 = row0 + 8;
#pragma unroll
        for (int ni = 0; ni < 4; ni++) {
            int col = wn + ni * 8 + 2 * tg;
            float2 b2 = *(const float2*)(bias + col);
            float v0 = acc[mi][ni][0] + b2.x;
            float v1 = acc[mi][ni][1] + b2.y;
            float v2 = acc[mi][ni][2] + b2.x;
            float v3 = acc[mi][ni][3] + b2.y;
            if (RELU) {
                v0 = fmaxf(v0, 0.f); v1 = fmaxf(v1, 0.f);
                v2 = fmaxf(v2, 0.f); v3 = fmaxf(v3, 0.f);
            }
            if (HALFOUT) {
                __half* Ch = (__half*)Call + (size_t)e * CAP * N;
                *(__half2*)(Ch + (size_t)row0 * N + bn + col) = __floats2half2_rn(v0, v1);
                *(__half2*)(Ch + (size_t)row1 * N + bn + col) = __floats2half2_rn(v2, v3);
            } else {
                float* Cf = (float*)Call + (size_t)e * CAP * N;
                float2 o0 = {v0, v1}, o1 = {v2, v3};
                *(float2*)(Cf + (size_t)row0 * N + bn + col) = o0;
                *(float2*)(Cf + (size_t)row1 * N + bn + col) = o1;
            }
        }
    }
}

// ---------------- 5) combine ------------------------
__global__ void combine_kernel(float* __restrict__ out) {
    int t = blockIdx.x;
    int i0 = 2 * t, i1 = 2 * t + 1;
    int e0 = g_item_e[i0], e1 = g_item_e[i1];
    int p0 = g_item_pos[i0], p1 = g_item_pos[i1];
    float w0 = (p0 < CAP) ? g_item_w[i0] : 0.f;
    float w1 = (p1 < CAP) ? g_item_w[i1] : 0.f;
    if (p0 >= CAP) p0 = CAP - 1;
    if (p1 >= CAP) p1 = CAP - 1;
    const float4* s0 = (const float4*)(g_oute + ((size_t)e0 * CAP + p0) * DM);
    const float4* s1 = (const float4*)(g_oute + ((size_t)e1 * CAP + p1) * DM);
    float4* dst = (float4*)(out + (size_t)t * DM);
    for (int j = threadIdx.x; j < DM/4; j += blockDim.x) {
        float4 a = s0[j], b = s1[j];
        float4 r;
        r.x = w0 * a.x + w1 * b.x;
        r.y = w0 * a.y + w1 * b.y;
        r.z = w0 * a.z + w1 * b.z;
        r.w = w0 * a.w + w1 * b.w;
        dst[j] = r;
    }
}

// ---------------- launcher --------------------------
extern "C" void kernel_launch(void* const* d_in, const int* in_sizes, int n_in,
                              void* d_out, int out_size) {
    const float* x  = (const float*)d_in[0];
    const float* gw = (const float*)d_in[1];
    const float* w1 = (const float*)d_in[2];
    const float* b1 = (const float*)d_in[3];
    const float* w2 = (const float*)d_in[4];
    const float* b2 = (const float*)d_in[5];
    float* out = (float*)d_out;

    void *pbuf, *ph, *poute, *pw1t, *pw2t;
    cudaGetSymbolAddress(&pbuf,  g_buf);
    cudaGetSymbolAddress(&ph,    g_h);
    cudaGetSymbolAddress(&poute, g_oute);
    cudaGetSymbolAddress(&pw1t,  g_w1t);
    cudaGetSymbolAddress(&pw2t,  g_w2t);

    cudaFuncSetAttribute(moe_gemm<true,  true >, cudaFuncAttributeMaxDynamicSharedMemorySize, GSMEM);
    cudaFuncSetAttribute(moe_gemm<false, false>, cudaFuncAttributeMaxDynamicSharedMemorySize, GSMEM);

    gating_kernel<<<T_TOKENS, 128>>>(x, gw);
    position_kernel<<<1, 256>>>();
    dispatch_kernel<<<NITEMS, 128>>>(x);

    // w1 [E][DM][DH] -> w1t half [E][DH][DM];  w2 [E][DH][DM] -> w2t half [E][DM][DH]
    transpose_cvt_half<<<dim3(DH/32, DM/32, NEXP), dim3(32, 8)>>>(w1, (__half*)pw1t, DM, DH);
    transpose_cvt_half<<<dim3(DM/32, DH/32, NEXP), dim3(32, 8)>>>(w2, (__half*)pw2t, DH, DM);

    // h = relu(buf @ w1 + b1): N=DH, K=DM
    moe_gemm<true,  true ><<<dim3(DH/128, CAP/128, NEXP), 256, GSMEM>>>(
        (const __half*)pbuf, (const __half*)pw1t, b1, ph, DH, DM);
    // oute = h @ w2 + b2: N=DM, K=DH
    moe_gemm<false, false><<<dim3(DM/128, CAP/128, NEXP), 256, GSMEM>>>(
        (const __half*)ph, (const __half*)pw2t, b2, poute, DM, DH);

    combine_kernel<<<T_TOKENS, 128>>>(out);
}

// round 11
// speedup vs baseline: 1.9464x; 1.0345x over previous
#include <cuda_runtime.h>
#include <cuda_fp16.h>
#include <cstdint>
#include <cstddef>

// ---------------- problem constants ----------------
#define T_TOKENS   8192
#define DM         2048
#define DH         8192
#define NEXP       8
#define CAP        2560
#define NITEMS     (T_TOKENS*2)

// ---------------- device scratch (static) ----------
__device__ __half g_buf [(size_t)NEXP*CAP*DM];      // dispatched x (fp16)
__device__ __half g_h   [(size_t)NEXP*CAP*DH];      // hidden (fp16)
__device__ float  g_oute[(size_t)NEXP*CAP*DM];      // expert outputs (fp32)
__device__ __half g_w1t [(size_t)NEXP*(size_t)DM*DH]; // w1^T: [E][DH][DM] fp16
__device__ __half g_w2t [(size_t)NEXP*(size_t)DM*DH]; // w2^T: [E][DM][DH] fp16
__device__ int    g_item_e  [NITEMS];
__device__ float  g_item_w  [NITEMS];
__device__ int    g_item_pos[NITEMS];
__device__ int    g_count   [NEXP];

// ---------------- helpers --------------------------
__device__ __forceinline__ uint32_t smem_u32(const void* p) {
    uint32_t a;
    asm("{ .reg .u64 t; cvta.to.shared.u64 t, %1; cvt.u32.u64 %0, t; }" : "=r"(a) : "l"(p));
    return a;
}
__device__ __forceinline__ void cpasync16(uint32_t dst, const void* src) {
    asm volatile("cp.async.cg.shared.global [%0], [%1], 16;" :: "r"(dst), "l"(src));
}
__device__ __forceinline__ void cp_commit() {
    asm volatile("cp.async.commit_group;" ::: "memory");
}
__device__ __forceinline__ void cp_wait1() {
    asm volatile("cp.async.wait_group 1;" ::: "memory");
}
__device__ __forceinline__ void cp_wait0() {
    asm volatile("cp.async.wait_group 0;" ::: "memory");
}
__device__ __forceinline__ void ldsm4(uint32_t* r, uint32_t addr) {
    asm volatile("ldmatrix.sync.aligned.m8n8.x4.shared.b16 {%0,%1,%2,%3}, [%4];"
        : "=r"(r[0]), "=r"(r[1]), "=r"(r[2]), "=r"(r[3]) : "r"(addr));
}
__device__ __forceinline__ void mma_f16(float* c, const uint32_t* a, const uint32_t* b) {
    asm volatile(
        "mma.sync.aligned.m16n8k16.row.col.f32.f16.f16.f32 "
        "{%0,%1,%2,%3}, {%4,%5,%6,%7}, {%8,%9}, {%0,%1,%2,%3};"
        : "+f"(c[0]), "+f"(c[1]), "+f"(c[2]), "+f"(c[3])
        : "r"(a[0]), "r"(a[1]), "r"(a[2]), "r"(a[3]), "r"(b[0]), "r"(b[1]));
}

// ---------------- 1) gating -------------------------
__global__ void gating_kernel(const float* __restrict__ x,
                              const float* __restrict__ gw) {
    int t = blockIdx.x;
    const float* xt = x + (size_t)t * DM;
    float acc[NEXP];
#pragma unroll
    for (int e = 0; e < NEXP; e++) acc[e] = 0.f;
    for (int d = threadIdx.x; d < DM; d += blockDim.x) {
        float xv = xt[d];
        const float* g = gw + (size_t)d * NEXP;
#pragma unroll
        for (int e = 0; e < NEXP; e++) acc[e] += xv * g[e];
    }
    __shared__ float red[NEXP][128];
#pragma unroll
    for (int e = 0; e < NEXP; e++) red[e][threadIdx.x] = acc[e];
    __syncthreads();
    for (int s = 64; s > 0; s >>= 1) {
        if (threadIdx.x < s) {
#pragma unroll
            for (int e = 0; e < NEXP; e++)
                red[e][threadIdx.x] += red[e][threadIdx.x + s];
        }
        __syncthreads();
    }
    if (threadIdx.x == 0) {
        float l[NEXP];
#pragma unroll
        for (int e = 0; e < NEXP; e++) l[e] = red[e][0];
        float m = l[0];
#pragma unroll
        for (int e = 1; e < NEXP; e++) m = fmaxf(m, l[e]);
        float p[NEXP]; float Z = 0.f;
#pragma unroll
        for (int e = 0; e < NEXP; e++) { p[e] = __expf(l[e] - m); Z += p[e]; }
        int i0 = 0;
#pragma unroll
        for (int e = 1; e < NEXP; e++) if (p[e] > p[i0]) i0 = e;
        int i1 = (i0 == 0) ? 1 : 0;
#pragma unroll
        for (int e = 0; e < NEXP; e++) if (e != i0 && p[e] > p[i1]) i1 = e;
        float w0 = p[i0] / Z, w1 = p[i1] / Z;
        float s = w0 + w1 + 1e-8f;
        g_item_e[2*t]   = i0;  g_item_e[2*t+1] = i1;
        g_item_w[2*t]   = w0 / s;
        g_item_w[2*t+1] = w1 / s;
    }
}

// ---------------- 2) serial positions ---------------
__global__ void position_kernel() {
    __shared__ int cnt[256][NEXP];
    int tid = threadIdx.x;
    int base = tid * (NITEMS / 256);
    int local[NEXP];
#pragma unroll
    for (int e = 0; e < NEXP; e++) local[e] = 0;
    for (int i = 0; i < NITEMS/256; i++) local[g_item_e[base + i]]++;
#pragma unroll
    for (int e = 0; e < NEXP; e++) cnt[tid][e] = local[e];
    __syncthreads();
    if (tid < NEXP) {
        int run = 0;
        for (int j = 0; j < 256; j++) { int c = cnt[j][tid]; cnt[j][tid] = run; run += c; }
        g_count[tid] = run < CAP ? run : CAP;
    }
    __syncthreads();
    int run[NEXP];
#pragma unroll
    for (int e = 0; e < NEXP; e++) run[e] = cnt[tid][e];
    for (int i = 0; i < NITEMS/256; i++) {
        int e = g_item_e[base + i];
        g_item_pos[base + i] = run[e]++;
    }
}

// ---------------- 3) dispatch (fp16 convert) --------
__global__ void dispatch_kernel(const float* __restrict__ x) {
    int i = blockIdx.x;
    int pos = g_item_pos[i];
    if (pos >= CAP) return;
    int e = g_item_e[i];
    int t = i >> 1;
    const float4* src = (const float4*)(x + (size_t)t * DM);
    __half2* dst = (__half2*)(g_buf + ((size_t)e * CAP + pos) * DM);
    for (int j = threadIdx.x; j < DM/4; j += blockDim.x) {
        float4 v = src[j];
        dst[2*j]   = __floats2half2_rn(v.x, v.y);
        dst[2*j+1] = __floats2half2_rn(v.z, v.w);
    }
}

// ---------------- 3b) weight transpose + fp16 -------
// in: [E][R][C] f32 -> out: [E][C][R] half
__global__ void transpose_cvt_half(const float* __restrict__ in,
                                   __half* __restrict__ out, int R, int C) {
    __shared__ float t[32][33];
    int e = blockIdx.z;
    const float* I = in + (size_t)e * R * C;
    __half* O = out + (size_t)e * R * C;
    int c0 = blockIdx.x * 32, r0 = blockIdx.y * 32;
    int tx = threadIdx.x, ty = threadIdx.y;   // block (32,8)
#pragma unroll
    for (int i = 0; i < 4; i++)
        t[ty + 8*i][tx] = I[(size_t)(r0 + ty + 8*i) * C + c0 + tx];
    __syncthreads();
    int p = ty * 32 + tx;
#pragma unroll
    for (int q = 0; q < 2; q++) {
        int pp = p + q * 256;
        int cl = pp >> 4, rp = pp & 15;
        __half2 h = __floats2half2_rn(t[2*rp][cl], t[2*rp+1][cl]);
        *(__half2*)(O + (size_t)(c0 + cl) * R + r0 + 2*rp) = h;
    }
}

// ---------------- 4) HMMA FP16 GEMM (ldmatrix) ------
// C[e] = act(A[e] @ Bt[e]^T + bias[e])
// A:[CAP][K] half (k-major), Bt:[N][K] half (k-major).
// CTA 128x128, K-step 64, 256 thr, 8 warps of 64x32, 3-stage cp.async,
// all fragments via ldmatrix.m8n8.x4.b16.
#define STGSZ 32768
#define GSMEM (3*STGSZ)   // 96 KB

template<bool RELU, bool HALFOUT>
__global__ void __launch_bounds__(256, 2)
moe_gemm(const __half* __restrict__ Aall, const __half* __restrict__ Btall,
         const float* __restrict__ biasall, void* __restrict__ Call,
         int N, int K) {
    int e  = blockIdx.z;
    int bm = blockIdx.y * 128;
    int bn = blockIdx.x * 128;
    if (bm >= g_count[e]) return;

    const __half* A  = Aall  + (size_t)e * CAP * K + (size_t)bm * K;
    const __half* Bt = Btall + (size_t)e * N * K + (size_t)bn * K;
    const float* bias = biasall + (size_t)e * N + bn;

    extern __shared__ char smem[];
    uint32_t sbase = smem_u32(smem);

    int tid = threadIdx.x;
    int wid = tid >> 5, lane = tid & 31;
    int gr = lane >> 2, tg = lane & 3;
    int wm = (wid & 1) * 64, wn = (wid >> 1) * 32;   // 2x4 warp grid, 64x32 tiles

    // ldmatrix per-lane decomposition
    int l7 = lane & 7;
    int lh = (lane >> 3) & 1;       // second 8-tile group
    int lq = lane >> 4;             // upper half of lanes

    // A: lane row = wm + 16mi + lh*8 + l7, chunk = (ch0 + lq) ^ (row&7)
    int aRowL = wm + lh * 8 + l7;                  // + 16*mi
    // B: lane n = wn + 16p + lq*8 + l7, chunk = (ch0 + lh) ^ (n&7)
    int bRowL = wn + lq * 8 + l7;                  // + 16*p

    // staging: row a_r (both A and Bt tiles), 2 threads per row, 4 chunks each
    int a_r = tid >> 1;             // 0..127
    int a_h = tid & 1;
    const __half* aRow = A  + (size_t)a_r * K;
    const __half* bRow = Bt + (size_t)a_r * K;

    float acc[4][4][4];
#pragma unroll
    for (int mi = 0; mi < 4; mi++)
#pragma unroll
        for (int ni = 0; ni < 4; ni++)
#pragma unroll
            for (int r = 0; r < 4; r++) acc[mi][ni][r] = 0.f;

    int NB = K / 64;

    auto stage = [&](int buf, int kbig) {
        uint32_t aDst = sbase + buf * STGSZ + a_r * 128;
        const __half* aSrc = aRow + kbig * 64;
#pragma unroll
        for (int j = 0; j < 4; j++) {
            int c = a_h * 4 + j;
            cpasync16(aDst + (((uint32_t)(c ^ (a_r & 7))) << 4), aSrc + c * 8);
        }
        uint32_t bDst = sbase + buf * STGSZ + 16384 + a_r * 128;
        const __half* bSrc = bRow + kbig * 64;
#pragma unroll
        for (int j = 0; j < 4; j++) {
            int c = a_h * 4 + j;
            cpasync16(bDst + (((uint32_t)(c ^ (a_r & 7))) << 4), bSrc + c * 8);
        }
    };

    stage(0, 0); cp_commit();
    stage(1, 1); cp_commit();

    int buf = 0;
    for (int big = 0; big < NB; big++) {
        if (big + 2 < NB) cp_wait1(); else cp_wait0();
        __syncthreads();   // single barrier per iteration

        if (big + 2 < NB) {
            int nbuf = buf + 2; if (nbuf >= 3) nbuf -= 3;
            stage(nbuf, big + 2);
            cp_commit();
        }

        uint32_t sA = sbase + buf * STGSZ;
        uint32_t sB = sA + 16384;
#pragma unroll
        for (int k16 = 0; k16 < 64; k16 += 16) {
            int ch0 = k16 >> 3;   // 0,2,4,6
            uint32_t a[4][4];
#pragma unroll
            for (int mi = 0; mi < 4; mi++) {
                int row = aRowL + mi * 16;
                uint32_t addr = sA + row * 128 + (((uint32_t)((ch0 + lq) ^ (row & 7))) << 4);
                ldsm4(a[mi], addr);
            }
            uint32_t b[4][2];
#pragma unroll
            for (int p = 0; p < 2; p++) {
                int n = bRowL + p * 16;
                uint32_t addr = sB + n * 128 + (((uint32_t)((ch0 + lh) ^ (n & 7))) << 4);
                uint32_t t4[4];
                ldsm4(t4, addr);
                b[2*p][0]   = t4[0];
                b[2*p][1]   = t4[1];
                b[2*p+1][0] = t4[2];
                b[2*p+1][1] = t4[3];
            }
#pragma unroll
            for (int mi = 0; mi < 4; mi++)
#pragma unroll
                for (int ni = 0; ni < 4; ni++)
                    mma_f16(acc[mi][ni], a[mi], b[ni]);
        }

        buf++; if (buf >= 3) buf = 0;
    }

    // epilogue
#pragma unroll
    for (int mi = 0; mi < 4; mi++) {
        int row0 = bm + wm + mi * 16 + gr;
        int row1 = row0 + 8;
#pragma unroll
        for (int ni = 0; ni < 4; ni++) {
            int col = wn + ni * 8 + 2 * tg;
            float2 b2 = *(const float2*)(bias + col);
            float v0 = acc[mi][ni][0] + b2.x;
            float v1 = acc[mi][ni][1] + b2.y;
            float v2 = acc[mi][ni][2] + b2.x;
            float v3 = acc[mi][ni][3] + b2.y;
            if (RELU) {
                v0 = fmaxf(v0, 0.f); v1 = fmaxf(v1, 0.f);
                v2 = fmaxf(v2, 0.f); v3 = fmaxf(v3, 0.f);
            }
            if (HALFOUT) {
                __half* Ch = (__half*)Call + (size_t)e * CAP * N;
                *(__half2*)(Ch + (size_t)row0 * N + bn + col) = __floats2half2_rn(v0, v1);
                *(__half2*)(Ch + (size_t)row1 * N + bn + col) = __floats2half2_rn(v2, v3);
            } else {
                float* Cf = (float*)Call + (size_t)e * CAP * N;
                float2 o0 = {v0, v1}, o1 = {v2, v3};
                *(float2*)(Cf + (size_t)row0 * N + bn + col) = o0;
                *(float2*)(Cf + (size_t)row1 * N + bn + col) = o1;
            }
        }
    }
}

// ---------------- 5) combine ------------------------
__global__ void combine_kernel(float* __restrict__ out) {
    int t = blockIdx.x;
    int i0 = 2 * t, i1 = 2 * t + 1;
    int e0 = g_item_e[i0], e1 = g_item_e[i1];
    int p0 = g_item_pos[i0], p1 = g_item_pos[i1];
    float w0 = (p0 < CAP) ? g_item_w[i0] : 0.f;
    float w1 = (p1 < CAP) ? g_item_w[i1] : 0.f;
    if (p0 >= CAP) p0 = CAP - 1;
    if (p1 >= CAP) p1 = CAP - 1;
    const float4* s0 = (const float4*)(g_oute + ((size_t)e0 * CAP + p0) * DM);
    const float4* s1 = (const float4*)(g_oute + ((size_t)e1 * CAP + p1) * DM);
    float4* dst = (float4*)(out + (size_t)t * DM);
    for (int j = threadIdx.x; j < DM/4; j += blockDim.x) {
        float4 a = s0[j], b = s1[j];
        float4 r;
        r.x = w0 * a.x + w1 * b.x;
        r.y = w0 * a.y + w1 * b.y;
        r.z = w0 * a.z + w1 * b.z;
        r.w = w0 * a.w + w1 * b.w;
        dst[j] = r;
    }
}

// ---------------- launcher --------------------------
extern "C" void kernel_launch(void* const* d_in, const int* in_sizes, int n_in,
                              void* d_out, int out_size) {
    const float* x  = (const float*)d_in[0];
    const float* gw = (const float*)d_in[1];
    const float* w1 = (const float*)d_in[2];
    const float* b1 = (const float*)d_in[3];
    const float* w2 = (const float*)d_in[4];
    const float* b2 = (const float*)d_in[5];
    float* out = (float*)d_out;

    void *pbuf, *ph, *poute, *pw1t, *pw2t;
    cudaGetSymbolAddress(&pbuf,  g_buf);
    cudaGetSymbolAddress(&ph,    g_h);
    cudaGetSymbolAddress(&poute, g_oute);
    cudaGetSymbolAddress(&pw1t,  g_w1t);
    cudaGetSymbolAddress(&pw2t,  g_w2t);

    cudaFuncSetAttribute(moe_gemm<true,  true >, cudaFuncAttributeMaxDynamicSharedMemorySize, GSMEM);
    cudaFuncSetAttribute(moe_gemm<false, false>, cudaFuncAttributeMaxDynamicSharedMemorySize, GSMEM);

    gating_kernel<<<T_TOKENS, 128>>>(x, gw);
    position_kernel<<<1, 256>>>();
    dispatch_kernel<<<NITEMS, 128>>>(x);

    // w1 [E][DM][DH] -> w1t half [E][DH][DM];  w2 [E][DH][DM] -> w2t half [E][DM][DH]
    transpose_cvt_half<<<dim3(DH/32, DM/32, NEXP), dim3(32, 8)>>>(w1, (__half*)pw1t, DM, DH);
    transpose_cvt_half<<<dim3(DM/32, DH/32, NEXP), dim3(32, 8)>>>(w2, (__half*)pw2t, DH, DM);

    // h = relu(buf @ w1 + b1): N=DH, K=DM
    moe_gemm<true,  true ><<<dim3(DH/128, CAP/128, NEXP), 256, GSMEM>>>(
        (const __half*)pbuf, (const __half*)pw1t, b1, ph, DH, DM);
    // oute = h @ w2 + b2: N=DM, K=DH
    moe_gemm<false, false><<<dim3(DM/128, CAP/128, NEXP), 256, GSMEM>>>(
        (const __half*)ph, (const __half*)pw2t, b2, poute, DM, DH);

    combine_kernel<<<T_TOKENS, 128>>>(out);
}